// round 15
// baseline (speedup 1.0000x reference)
#include <cuda_runtime.h>
#include <cuda_fp16.h>
#include <cstdint>
#include <math.h>

// logits = x @ W^T + b ; softmax ; top-2 ; renormalize.
// fp16 split GEMM (hh+hl+lh) via mma.sync m16n8k16.
// R15: two co-resident CTAs per SM with small footprint.
//   BM=64, KC=32, 61.5KB smem/CTA (123KB for 2 CTAs, L1 keeps ~105KB),
//   320 thr = 8 consumer warps (2Mx4N, 32x32 tiles, R14 frag double-buffer)
//   + 2 producer warps. Grid 256 fills all 148 SMs. R9 mbarrier protocol.
// out[0:2T) = indices (as f32), out[2T:4T) = renormalized probs.

static constexpr int D_K  = 4096;
static constexpr int NE   = 128;
static constexpr int BM   = 64;                // tokens per CTA
static constexpr int KC   = 32;                // k per chunk
static constexpr int NCH  = D_K / KC;          // 128
static constexpr int RS   = 40;                // halves per smem row (32 + 8 pad)
static constexpr int HTA  = BM * RS * 2;       // 5120 B  (A half-tile)
static constexpr int HTB  = NE * RS * 2;       // 10240 B (B half-tile)
static constexpr int STGA = 2 * HTA;           // 10240
static constexpr int STGB = 2 * HTB;           // 20480
static constexpr int A_OFF = 0;                // 2 stages: [0, 20480)
static constexpr int B_OFF = 2 * STGA;         // 2 stages: [20480, 61440)
static constexpr int MB_OFF = 2 * STGA + 2 * STGB;   // 61440
static constexpr int SMEM_TOTAL = MB_OFF + 64;        // 61504
static constexpr float WSCALE  = 64.0f;
static constexpr float IWSCALE = 1.0f / 64.0f;

__device__ __half2 gWhi[NE * D_K / 2];
__device__ __half2 gWlo[NE * D_K / 2];

__global__ void __launch_bounds__(256)
convW(const float* __restrict__ W)
{
    int i = blockIdx.x * 256 + threadIdx.x;
    float2 w = reinterpret_cast<const float2*>(W)[i];
    float ax = w.x * WSCALE, ay = w.y * WSCALE;
    __half hx = __float2half_rn(ax), hy = __float2half_rn(ay);
    gWhi[i] = __halves2half2(hx, hy);
    gWlo[i] = __floats2half2_rn(ax - __half2float(hx), ay - __half2float(hy));
}

__device__ __forceinline__ uint32_t smem_u32(const void* p) {
    uint32_t a;
    asm("{ .reg .u64 t; cvta.to.shared.u64 t, %1; cvt.u32.u64 %0, t; }" : "=r"(a) : "l"(p));
    return a;
}

#define LDM4(r, addr)                                                            \
    asm volatile("ldmatrix.sync.aligned.m8n8.x4.shared.b16 {%0,%1,%2,%3}, [%4];" \
                 : "=r"((r)[0]), "=r"((r)[1]), "=r"((r)[2]), "=r"((r)[3])        \
                 : "r"(addr))

#define MMA16816(c, a, b0, b1)                                               \
    asm volatile("mma.sync.aligned.m16n8k16.row.col.f32.f16.f16.f32 "        \
                 "{%0,%1,%2,%3}, {%4,%5,%6,%7}, {%8,%9}, {%0,%1,%2,%3};"     \
                 : "+f"((c)[0]), "+f"((c)[1]), "+f"((c)[2]), "+f"((c)[3])    \
                 : "r"((a)[0]), "r"((a)[1]), "r"((a)[2]), "r"((a)[3]),       \
                   "r"(b0), "r"(b1))

#define CP16(dst, src) \
    asm volatile("cp.async.cg.shared.global [%0], [%1], 16;" :: "r"(dst), "l"(src))

__device__ __forceinline__ void mbar_init(uint32_t a, uint32_t cnt) {
    asm volatile("mbarrier.init.shared.b64 [%0], %1;" :: "r"(a), "r"(cnt) : "memory");
}
__device__ __forceinline__ void mbar_arrive(uint32_t a) {
    asm volatile("mbarrier.arrive.release.cta.shared::cta.b64 _, [%0];" :: "r"(a) : "memory");
}
__device__ __forceinline__ void mbar_wait(uint32_t a, uint32_t parity) {
    asm volatile(
        "{\n\t.reg .pred P1;\n\t"
        "W%=:\n\t"
        "mbarrier.try_wait.parity.acquire.cta.shared::cta.b64 P1, [%0], %1, 0x989680;\n\t"
        "@P1 bra.uni DONE%=;\n\t"
        "bra.uni W%=;\n\t"
        "DONE%=:\n\t}"
        :: "r"(a), "r"(parity) : "memory");
}

__device__ __forceinline__ uint32_t pack_hi(float a, float b, float& la, float& lb) {
    __half ha = __float2half_rn(a);
    __half hb = __float2half_rn(b);
    la = a - __half2float(ha);
    lb = b - __half2float(hb);
    __half2 h = __halves2half2(ha, hb);
    return *reinterpret_cast<uint32_t*>(&h);
}
__device__ __forceinline__ uint32_t pack_lo(float a, float b) {
    __half2 h = __floats2half2_rn(a, b);
    return *reinterpret_cast<uint32_t*>(&h);
}

__global__ void __launch_bounds__(320, 2)
router_mma(const float* __restrict__ x, const float* __restrict__ bias,
           float* __restrict__ out, int T)
{
    extern __shared__ char smem[];
    const uint32_t sbase = smem_u32(smem);
    const int tid  = threadIdx.x;
    const int wid  = tid >> 5, lane = tid & 31;
    const int t0   = blockIdx.x * BM;

    const uint32_t mFull0 = sbase + MB_OFF, mFull1 = mFull0 + 8;
    const uint32_t mEmp0  = mFull0 + 16,    mEmp1  = mFull0 + 24;
    if (tid == 0) {
        mbar_init(mFull0, 64);  mbar_init(mFull1, 64);    // 2 producer warps
        mbar_init(mEmp0, 256);  mbar_init(mEmp1, 256);    // 8 consumer warps
    }
    __syncthreads();

    if (wid >= 8) {
        // ================= PRODUCER (2 warps, 64 threads) =================
        const int ptid = tid - 256;
        const char* whiB = reinterpret_cast<const char*>(gWhi);
        const char* wloB = reinterpret_cast<const char*>(gWlo);

        // A chunk = 64x32 f32 = 512 float4 -> 8 per thread
        float4 araw[8];
        auto fetchA = [&](int cc) {
            const int k0 = cc * KC;
#pragma unroll
            for (int j = 0; j < 8; j++) {
                int i = ptid + j * 64, row = i >> 3, c4 = i & 7;
                araw[j] = *reinterpret_cast<const float4*>(
                    x + (size_t)(t0 + row) * D_K + k0 + c4 * 4);
            }
        };
        auto stsA = [&](int st) {
            char* base = smem + A_OFF + st * STGA;
#pragma unroll
            for (int j = 0; j < 8; j++) {
                int i = ptid + j * 64, row = i >> 3, c4 = i & 7;
                uint32_t off = (uint32_t)row * (RS * 2) + c4 * 8;
                float lx, ly, lz, lw;
                uint2 hi, lo;
                hi.x = pack_hi(araw[j].x, araw[j].y, lx, ly);
                hi.y = pack_hi(araw[j].z, araw[j].w, lz, lw);
                lo.x = pack_lo(lx, ly); lo.y = pack_lo(lz, lw);
                *reinterpret_cast<uint2*>(base + off)       = hi;
                *reinterpret_cast<uint2*>(base + HTA + off) = lo;
            }
        };
        // B half-tile = 128 rows x 64 B = 512 16B lines -> 8 per thread per half
        auto fillB = [&](int cc, int st) {
            const uint32_t sdst = sbase + B_OFF + st * STGB;
            const int kByte = cc * KC * 2;
#pragma unroll
            for (int t = 0; t < 8; t++) {
                int i   = ptid + t * 64;
                int row = i >> 2, c16 = i & 3;
                uint32_t d = sdst + row * (RS * 2) + c16 * 16;
                size_t  go = (size_t)row * (D_K * 2) + kByte + c16 * 16;
                CP16(d,       whiB + go);
                CP16(d + HTB, wloB + go);
            }
            asm volatile("cp.async.commit_group;" ::: "memory");
        };

        int pe[2] = {0, 0};
        fetchA(0);
        for (int c = 0; c < NCH; c++) {
            const int s = c & 1;
            const uint32_t mE = s ? mEmp1 : mEmp0;
            const uint32_t mF = s ? mFull1 : mFull0;
            if (c >= 2) { mbar_wait(mE, pe[s]); pe[s] ^= 1; }
            stsA(s);
            fillB(c, s);
            if (c + 1 < NCH) fetchA(c + 1);
            asm volatile("cp.async.wait_group 0;" ::: "memory");
            mbar_arrive(mF);
        }
        return;
    }

    // ===== CONSUMER (8 warps, 256 threads) — R14 double-buffered frags =====
    const int wm = wid >> 2;     // 2 M-groups (32 tokens)
    const int wn = wid & 3;      // 4 N-groups (32 experts)

    float acc[2][4][4];          // [mt][n8][frag] = 32 regs
#pragma unroll
    for (int i = 0; i < 2; i++)
#pragma unroll
        for (int j = 0; j < 4; j++)
#pragma unroll
            for (int k = 0; k < 4; k++) acc[i][j][k] = 0.0f;

    const int ltile = lane >> 3, lr = lane & 7;
    const int lmoff = ((ltile & 1) * 8 + lr) * RS + (ltile >> 1) * 8;

    uint32_t Ah[2][4], Al[2][4];          // [buf] per (kk,mt) step
    uint32_t Bh[2][2][4], Bl[2][2][4];    // [buf][g] per kk

    int cf[2] = {0, 0};
    for (int c = 0; c < NCH; c++) {
        const int s = c & 1;
        const uint32_t mF = s ? mFull1 : mFull0;
        const uint32_t mE = s ? mEmp1 : mEmp0;
        mbar_wait(mF, cf[s]); cf[s] ^= 1;

        const uint32_t aH = sbase + A_OFF + s * STGA;
        const uint32_t bH = sbase + B_OFF + s * STGB;

        // prologue: fragments for (kk=0, mt=0) + B(kk=0)
        {
            uint32_t offA = (uint32_t)((wm * 32) * RS + lmoff) * 2;
            LDM4(Ah[0], aH + offA);
            LDM4(Al[0], aH + HTA + offA);
#pragma unroll
            for (int g = 0; g < 2; g++) {
                uint32_t offB = (uint32_t)((wn * 32 + g * 16) * RS + lmoff) * 2;
                LDM4(Bh[0][g], bH + offB);
                LDM4(Bl[0][g], bH + HTB + offB);
            }
        }

#pragma unroll
        for (int st = 0; st < 4; st++) {       // st = kk*2 + mt
            const int kk = st >> 1, mt = st & 1;
            const int ab = st & 1;             // A buffer
            const int bb = kk & 1;             // B buffer

            // prefetch next step's fragments
            if (mt < 1) {
                uint32_t offA = (uint32_t)((wm * 32 + 16) * RS + kk * 16 + lmoff) * 2;
                LDM4(Ah[ab ^ 1], aH + offA);
                LDM4(Al[ab ^ 1], aH + HTA + offA);
            } else if (kk < 1) {
                uint32_t offA = (uint32_t)((wm * 32) * RS + 16 + lmoff) * 2;
                LDM4(Ah[ab ^ 1], aH + offA);
                LDM4(Al[ab ^ 1], aH + HTA + offA);
#pragma unroll
                for (int g = 0; g < 2; g++) {
                    uint32_t offB = (uint32_t)((wn * 32 + g * 16) * RS + 16 + lmoff) * 2;
                    LDM4(Bh[bb ^ 1][g], bH + offB);
                    LDM4(Bl[bb ^ 1][g], bH + HTB + offB);
                }
            }

            // 12 MMAs for this step
#pragma unroll
            for (int g = 0; g < 2; g++)
#pragma unroll
                for (int r = 0; r < 2; r++) {
                    float* a = acc[mt][g * 2 + r];
                    MMA16816(a, Ah[ab], Bh[bb][g][r], Bh[bb][g][r + 2]);
                    MMA16816(a, Ah[ab], Bl[bb][g][r], Bl[bb][g][r + 2]);
                    MMA16816(a, Al[ab], Bh[bb][g][r], Bh[bb][g][r + 2]);
                }
        }
        mbar_arrive(mE);
    }

    // ---- epilogue (consumers only) ----
    asm volatile("bar.sync 1, 256;" ::: "memory");

    float* lg = reinterpret_cast<float*>(smem);   // pitch 129, 64 rows = 33024 B
    const int lr4 = lane >> 2, lc2 = (lane & 3) * 2;
#pragma unroll
    for (int mt = 0; mt < 2; mt++)
#pragma unroll
        for (int nt = 0; nt < 4; nt++)
#pragma unroll
            for (int di = 0; di < 4; di++) {
                int row = wm * 32 + mt * 16 + lr4 + (di >> 1) * 8;
                int col = wn * 32 + nt * 8 + lc2 + (di & 1);
                lg[row * 129 + col] = acc[mt][nt][di] * IWSCALE + __ldg(&bias[col]);
            }
    asm volatile("bar.sync 1, 256;" ::: "memory");

    if (tid < BM) {
        const float* row = &lg[tid * 129];
        float v1 = -INFINITY, v2 = -INFINITY;
        int   i1 = 0, i2 = 0;
#pragma unroll 4
        for (int e = 0; e < NE; e++) {
            float v = row[e];
            if (v > v1)      { v2 = v1; i2 = i1; v1 = v; i1 = e; }
            else if (v > v2) { v2 = v;  i2 = e; }
        }
        float ssum = 0.0f;
#pragma unroll 4
        for (int e = 0; e < NE; e++) ssum += __expf(row[e] - v1);
        float p1 = 1.0f / ssum;
        float p2 = __expf(v2 - v1) / ssum;
        float den = p1 + p2 + 1e-8f;
        int t = t0 + tid;
        out[(size_t)t * 2 + 0] = (float)i1;
        out[(size_t)t * 2 + 1] = (float)i2;
        out[(size_t)2 * T + (size_t)t * 2 + 0] = p1 / den;
        out[(size_t)2 * T + (size_t)t * 2 + 1] = p2 / den;
    }
}

extern "C" void kernel_launch(void* const* d_in, const int* in_sizes, int n_in,
                              void* d_out, int out_size)
{
    const float* x = (const float*)d_in[0];
    const float* W = (const float*)d_in[1];
    const float* b = (const float*)d_in[2];
    float* out = (float*)d_out;

    int E = in_sizes[2];            // 128
    int D = in_sizes[1] / E;        // 4096
    int T = in_sizes[0] / D;        // 16384

    static int configured = -1;
    if (configured < 0) {
        cudaFuncSetAttribute(router_mma, cudaFuncAttributeMaxDynamicSharedMemorySize,
                             SMEM_TOTAL);
        configured = 1;
    }
    convW<<<(E * D / 2) / 256, 256>>>(W);
    router_mma<<<T / BM, 320, SMEM_TOTAL>>>(x, b, out, T);
}

// round 16
// speedup vs baseline: 1.0613x; 1.0613x over previous
#include <cuda_runtime.h>
#include <cuda_fp16.h>
#include <cstdint>
#include <math.h>

// logits = x @ W^T + b ; softmax ; top-2 ; renormalize.
// fp16 split GEMM (hh+hl+lh) via mma.sync m16n8k16.
// R16 = R14 EXACT (384 thr, 8 consumer warps w/ frag double-buffer + 4
// producer warps, 2-stage mbarrier handoff, 147KB smem) with ONE delta:
//   producer issues cp.async B (fillB) BEFORE the A convert (stsA), so the
//   ~600-cycle copy latency is hidden under the convert instead of being
//   exposed at wait_group.
// out[0:2T) = indices (as f32), out[2T:4T) = renormalized probs.

static constexpr int D_K  = 4096;
static constexpr int NE   = 128;
static constexpr int BM   = 128;
static constexpr int KC   = 64;
static constexpr int NCH  = D_K / KC;          // 64
static constexpr int RS   = 72;                // halves per smem row (64 + 8 pad)
static constexpr int HT   = 128 * RS * 2;      // 18432 B per half-tile
static constexpr int STG  = 2 * HT;            // hi+lo = 36864 B
static constexpr int A_OFF = 0;                // A stages: [0, 73728)
static constexpr int B_OFF = 2 * STG;          // B stages: [73728, 147456)
static constexpr int MB_OFF = 4 * STG;
static constexpr int SMEM_TOTAL = 4 * STG + 64;   // 147520
static constexpr float WSCALE  = 64.0f;
static constexpr float IWSCALE = 1.0f / 64.0f;

__device__ __half2 gWhi[NE * D_K / 2];
__device__ __half2 gWlo[NE * D_K / 2];

__global__ void __launch_bounds__(256)
convW(const float* __restrict__ W)
{
    int i = blockIdx.x * 256 + threadIdx.x;
    float2 w = reinterpret_cast<const float2*>(W)[i];
    float ax = w.x * WSCALE, ay = w.y * WSCALE;
    __half hx = __float2half_rn(ax), hy = __float2half_rn(ay);
    gWhi[i] = __halves2half2(hx, hy);
    gWlo[i] = __floats2half2_rn(ax - __half2float(hx), ay - __half2float(hy));
}

__device__ __forceinline__ uint32_t smem_u32(const void* p) {
    uint32_t a;
    asm("{ .reg .u64 t; cvta.to.shared.u64 t, %1; cvt.u32.u64 %0, t; }" : "=r"(a) : "l"(p));
    return a;
}

#define LDM4(r, addr)                                                            \
    asm volatile("ldmatrix.sync.aligned.m8n8.x4.shared.b16 {%0,%1,%2,%3}, [%4];" \
                 : "=r"((r)[0]), "=r"((r)[1]), "=r"((r)[2]), "=r"((r)[3])        \
                 : "r"(addr))

#define MMA16816(c, a, b0, b1)                                               \
    asm volatile("mma.sync.aligned.m16n8k16.row.col.f32.f16.f16.f32 "        \
                 "{%0,%1,%2,%3}, {%4,%5,%6,%7}, {%8,%9}, {%0,%1,%2,%3};"     \
                 : "+f"((c)[0]), "+f"((c)[1]), "+f"((c)[2]), "+f"((c)[3])    \
                 : "r"((a)[0]), "r"((a)[1]), "r"((a)[2]), "r"((a)[3]),       \
                   "r"(b0), "r"(b1))

#define CP16(dst, src) \
    asm volatile("cp.async.cg.shared.global [%0], [%1], 16;" :: "r"(dst), "l"(src))

__device__ __forceinline__ void mbar_init(uint32_t a, uint32_t cnt) {
    asm volatile("mbarrier.init.shared.b64 [%0], %1;" :: "r"(a), "r"(cnt) : "memory");
}
__device__ __forceinline__ void mbar_arrive(uint32_t a) {
    asm volatile("mbarrier.arrive.release.cta.shared::cta.b64 _, [%0];" :: "r"(a) : "memory");
}
__device__ __forceinline__ void mbar_wait(uint32_t a, uint32_t parity) {
    asm volatile(
        "{\n\t.reg .pred P1;\n\t"
        "W%=:\n\t"
        "mbarrier.try_wait.parity.acquire.cta.shared::cta.b64 P1, [%0], %1, 0x989680;\n\t"
        "@P1 bra.uni DONE%=;\n\t"
        "bra.uni W%=;\n\t"
        "DONE%=:\n\t}"
        :: "r"(a), "r"(parity) : "memory");
}

__device__ __forceinline__ uint32_t pack_hi(float a, float b, float& la, float& lb) {
    __half ha = __float2half_rn(a);
    __half hb = __float2half_rn(b);
    la = a - __half2float(ha);
    lb = b - __half2float(hb);
    __half2 h = __halves2half2(ha, hb);
    return *reinterpret_cast<uint32_t*>(&h);
}
__device__ __forceinline__ uint32_t pack_lo(float a, float b) {
    __half2 h = __floats2half2_rn(a, b);
    return *reinterpret_cast<uint32_t*>(&h);
}

__global__ void __launch_bounds__(384, 1)
router_mma(const float* __restrict__ x, const float* __restrict__ bias,
           float* __restrict__ out, int T)
{
    extern __shared__ char smem[];
    const uint32_t sbase = smem_u32(smem);
    const int tid  = threadIdx.x;
    const int wid  = tid >> 5, lane = tid & 31;
    const int t0   = blockIdx.x * BM;

    const uint32_t mFull0 = sbase + MB_OFF, mFull1 = mFull0 + 8;
    const uint32_t mEmp0  = mFull0 + 16,    mEmp1  = mFull0 + 24;
    if (tid == 0) {
        mbar_init(mFull0, 128); mbar_init(mFull1, 128);
        mbar_init(mEmp0, 256);  mbar_init(mEmp1, 256);
    }
    __syncthreads();

    if (wid >= 8) {
        // ================= PRODUCER (4 warps, 128 threads) =================
        const int ptid = tid - 256;
        const char* whiB = reinterpret_cast<const char*>(gWhi);
        const char* wloB = reinterpret_cast<const char*>(gWlo);

        float4 araw[16];
        auto fetchA = [&](int cc) {
            const int k0 = cc * KC;
#pragma unroll
            for (int j = 0; j < 16; j++) {
                int i = ptid + j * 128, row = i >> 4, c4 = i & 15;
                araw[j] = *reinterpret_cast<const float4*>(
                    x + (size_t)(t0 + row) * D_K + k0 + c4 * 4);
            }
        };
        auto stsA = [&](int st) {
            char* base = smem + A_OFF + st * STG;
#pragma unroll
            for (int j = 0; j < 16; j++) {
                int i = ptid + j * 128, row = i >> 4, c4 = i & 15;
                uint32_t off = (uint32_t)row * (RS * 2) + c4 * 8;
                float lx, ly, lz, lw;
                uint2 hi, lo;
                hi.x = pack_hi(araw[j].x, araw[j].y, lx, ly);
                hi.y = pack_hi(araw[j].z, araw[j].w, lz, lw);
                lo.x = pack_lo(lx, ly); lo.y = pack_lo(lz, lw);
                *reinterpret_cast<uint2*>(base + off)      = hi;
                *reinterpret_cast<uint2*>(base + HT + off) = lo;
            }
        };
        auto fillB = [&](int cc, int st) {
            const uint32_t sdst = sbase + B_OFF + st * STG;
            const int kByte = cc * KC * 2;
#pragma unroll
            for (int t = 0; t < 8; t++) {
                int i   = ptid + t * 128;
                int row = i >> 3, c16 = i & 7;
                uint32_t d = sdst + row * (RS * 2) + c16 * 16;
                size_t  go = (size_t)row * (D_K * 2) + kByte + c16 * 16;
                CP16(d,      whiB + go);
                CP16(d + HT, wloB + go);
            }
            asm volatile("cp.async.commit_group;" ::: "memory");
        };

        int pe[2] = {0, 0};
        fetchA(0);
        for (int c = 0; c < NCH; c++) {
            const int s = c & 1;
            const uint32_t mE = s ? mEmp1 : mEmp0;
            const uint32_t mF = s ? mFull1 : mFull0;
            if (c >= 2) { mbar_wait(mE, pe[s]); pe[s] ^= 1; }
            fillB(c, s);        // cp.asyncs fly during the convert below
            stsA(s);            // ~600 cyc of convert hides the copy latency
            if (c + 1 < NCH) fetchA(c + 1);
            asm volatile("cp.async.wait_group 0;" ::: "memory");
            mbar_arrive(mF);
        }
        return;
    }

    // ====== CONSUMER (8 warps) — R14 VERBATIM (pipelined fragments) ======
    const int wm = wid >> 2;     // 2 M-groups (64 tokens)
    const int wn = wid & 3;      // 4 N-groups (32 experts)

    float acc[4][4][4];          // [mt][n8][frag]
#pragma unroll
    for (int i = 0; i < 4; i++)
#pragma unroll
        for (int j = 0; j < 4; j++)
#pragma unroll
            for (int k = 0; k < 4; k++) acc[i][j][k] = 0.0f;

    const int ltile = lane >> 3, lr = lane & 7;
    const int lmoff = ((ltile & 1) * 8 + lr) * RS + (ltile >> 1) * 8;

    uint32_t Ah[2][4], Al[2][4];          // [buf][reg] — per (kk,mt) step
    uint32_t Bh[2][2][4], Bl[2][2][4];    // [buf][g][reg] — per kk

    int cf[2] = {0, 0};
    for (int c = 0; c < NCH; c++) {
        const int s = c & 1;
        const uint32_t mF = s ? mFull1 : mFull0;
        const uint32_t mE = s ? mEmp1 : mEmp0;
        mbar_wait(mF, cf[s]); cf[s] ^= 1;

        const uint32_t aH = sbase + A_OFF + s * STG;
        const uint32_t bH = sbase + B_OFF + s * STG;

        // prologue: fragments for step 0 (kk=0, mt=0) + B(kk=0)
        {
            uint32_t offA = (uint32_t)((wm * 64) * RS + lmoff) * 2;
            LDM4(Ah[0], aH + offA);
            LDM4(Al[0], aH + HT + offA);
#pragma unroll
            for (int g = 0; g < 2; g++) {
                uint32_t offB = (uint32_t)((wn * 32 + g * 16) * RS + lmoff) * 2;
                LDM4(Bh[0][g], bH + offB);
                LDM4(Bl[0][g], bH + HT + offB);
            }
        }

#pragma unroll
        for (int st = 0; st < 16; st++) {      // st = kk*4 + mt
            const int kk = st >> 2, mt = st & 3;
            const int ab = st & 1;             // A buffer for this step
            const int bb = kk & 1;             // B buffer for this kk

            if (mt < 3) {
                uint32_t offA = (uint32_t)((wm * 64 + (mt + 1) * 16) * RS
                                           + kk * 16 + lmoff) * 2;
                LDM4(Ah[ab ^ 1], aH + offA);
                LDM4(Al[ab ^ 1], aH + HT + offA);
            } else if (kk < 3) {
                uint32_t offA = (uint32_t)((wm * 64) * RS + (kk + 1) * 16 + lmoff) * 2;
                LDM4(Ah[ab ^ 1], aH + offA);
                LDM4(Al[ab ^ 1], aH + HT + offA);
#pragma unroll
                for (int g = 0; g < 2; g++) {
                    uint32_t offB = (uint32_t)((wn * 32 + g * 16) * RS
                                               + (kk + 1) * 16 + lmoff) * 2;
                    LDM4(Bh[bb ^ 1][g], bH + offB);
                    LDM4(Bl[bb ^ 1][g], bH + HT + offB);
                }
            }

#pragma unroll
            for (int g = 0; g < 2; g++)
#pragma unroll
                for (int r = 0; r < 2; r++) {
                    float* a = acc[mt][g * 2 + r];
                    MMA16816(a, Ah[ab], Bh[bb][g][r], Bh[bb][g][r + 2]);
                    MMA16816(a, Ah[ab], Bl[bb][g][r], Bl[bb][g][r + 2]);
                    MMA16816(a, Al[ab], Bh[bb][g][r], Bh[bb][g][r + 2]);
                }
        }
        mbar_arrive(mE);
    }

    // ---- epilogue (consumers only) ----
    asm volatile("bar.sync 1, 256;" ::: "memory");

    float* lg = reinterpret_cast<float*>(smem);   // pitch 129, 66048 B
    const int lr4 = lane >> 2, lc2 = (lane & 3) * 2;
#pragma unroll
    for (int mt = 0; mt < 4; mt++)
#pragma unroll
        for (int nt = 0; nt < 4; nt++)
#pragma unroll
            for (int di = 0; di < 4; di++) {
                int row = wm * 64 + mt * 16 + lr4 + (di >> 1) * 8;
                int col = wn * 32 + nt * 8 + lc2 + (di & 1);
                lg[row * 129 + col] = acc[mt][nt][di] * IWSCALE + __ldg(&bias[col]);
            }
    asm volatile("bar.sync 1, 256;" ::: "memory");

    if (tid < BM) {
        const float* row = &lg[tid * 129];
        float v1 = -INFINITY, v2 = -INFINITY;
        int   i1 = 0, i2 = 0;
#pragma unroll 4
        for (int e = 0; e < NE; e++) {
            float v = row[e];
            if (v > v1)      { v2 = v1; i2 = i1; v1 = v; i1 = e; }
            else if (v > v2) { v2 = v;  i2 = e; }
        }
        float ssum = 0.0f;
#pragma unroll 4
        for (int e = 0; e < NE; e++) ssum += __expf(row[e] - v1);
        float p1 = 1.0f / ssum;
        float p2 = __expf(v2 - v1) / ssum;
        float den = p1 + p2 + 1e-8f;
        int t = t0 + tid;
        out[(size_t)t * 2 + 0] = (float)i1;
        out[(size_t)t * 2 + 1] = (float)i2;
        out[(size_t)2 * T + (size_t)t * 2 + 0] = p1 / den;
        out[(size_t)2 * T + (size_t)t * 2 + 1] = p2 / den;
    }
}

extern "C" void kernel_launch(void* const* d_in, const int* in_sizes, int n_in,
                              void* d_out, int out_size)
{
    const float* x = (const float*)d_in[0];
    const float* W = (const float*)d_in[1];
    const float* b = (const float*)d_in[2];
    float* out = (float*)d_out;

    int E = in_sizes[2];            // 128
    int D = in_sizes[1] / E;        // 4096
    int T = in_sizes[0] / D;        // 16384

    static int configured = -1;
    if (configured < 0) {
        cudaFuncSetAttribute(router_mma, cudaFuncAttributeMaxDynamicSharedMemorySize,
                             SMEM_TOTAL);
        configured = 1;
    }
    convW<<<(E * D / 2) / 256, 256>>>(W);
    router_mma<<<T / BM, 384, SMEM_TOTAL>>>(x, b, out, T);
}